// round 14
// baseline (speedup 1.0000x reference)
#include <cuda_runtime.h>

#define NP   4096   // particle capacity
#define NCX  8      // 8^3 cells of size 2R
#define NC   512
#define CAP  96     // slots per cell (mean ~33 for this data)
#define NBLK 256    // persistent blocks (2/SM co-resident guaranteed)
#define NG   (NP / 4)   // 1024 particle groups (4 per block per phase pass)

static constexpr float R_      = 0.1f;
static constexpr float DT_     = 1.0f / 60.0f;
static constexpr float MAXV    = 3.0f;                 // 0.5*0.1/DT
static constexpr float RHO0    = 17510.1f;
static constexpr float STIFF   = 2.99e-11f;
static constexpr float SPIKY   = 4.774648292756860e6f; // 15/(pi*R^6)
static constexpr float NSPIKY3 = -3.0f * 4.774648292756860e6f;
static constexpr float VDTR    = 60.0f * (1.0f / 60.0f) / 17510.1f; // VISC*DT/RHO0
static constexpr float EPS_    = 1e-8f;
// self-pair contribution to rho: d_self = sqrt(EPS) = 1e-4, t = R - 1e-4
static constexpr float W_SELF  =
    (float)(4.774648292756860e6 * 0.0999 * 0.0999 * 0.0999);

// ---------------- scratch (device globals: allocation-guard safe) -----------
__device__ float    g_px[NP], g_py[NP], g_pz[NP];   // current pred (orig order)
__device__ float    g_lam[NP];
__device__ float    g_nvx[NP], g_nvy[NP], g_nvz[NP];
__device__ int      g_cnt[4][NC];                   // per-grid counts (zero-init)
__device__ float4   g_slot[4][NC * CAP];            // pos.xyz + (lambda in .w)
__device__ int      g_sidx[4][NP];                  // particle -> slot index
__device__ float4   g_nvslot[NC * CAP];             // new_vel slots (grid 3)
__device__ int      g_bar_cnt;                      // global barrier state
__device__ unsigned g_bar_gen;

// ---------------- global barrier (sense-reversing, device-scope) ------------
__device__ __forceinline__ void gbar() {
    __syncthreads();
    if (threadIdx.x == 0) {
        __threadfence();
        unsigned gen = atomicAdd(&g_bar_gen, 0u);
        if (atomicAdd(&g_bar_cnt, 1) == (int)gridDim.x - 1) {
            atomicExch(&g_bar_cnt, 0);
            __threadfence();
            atomicAdd(&g_bar_gen, 1u);
        } else {
            while (atomicAdd(&g_bar_gen, 0u) == gen) { __nanosleep(64); }
            __threadfence();    // acquire: order subsequent reads
        }
    }
    __syncthreads();
}

// ---------------- cell helpers (cell size = 2R = 0.2) -----------------------
// every coordinate clamped AT USE: h < 512 for ANY input bits (hardening)
__device__ __forceinline__ int clampi(int v) { return min(max(v, 0), NCX - 1); }
__device__ __forceinline__ int ccell(float x) {          // insertion cell
    return clampi(__float2int_rd(x * 5.0f) + 1);
}
__device__ __forceinline__ int pcoord(float x, int d) {  // probe cell, clamped
    return clampi(__float2int_rd(x * 5.0f - 0.5f) + 1 + d);
}
__device__ __forceinline__ int bidx3(int ix, int iy, int iz) {
    return ix | (iy << 3) | (iz << 6);
}
__device__ __forceinline__ int grid_insert(int g, float x, float y, float z) {
    int h = bidx3(ccell(x), ccell(y), ccell(z));         // h < 512 always
    int s = atomicAdd(&g_cnt[g][h], 1);
    if (s >= CAP) return -1;
    int si = h * CAP + s;                                // < NC*CAP
    g_slot[g][si] = make_float4(x, y, z, 0.0f);
    return si;
}

__device__ __forceinline__ float wred(float v) {
#pragma unroll
    for (int o = 16; o; o >>= 1) v += __shfl_xor_sync(0xffffffffu, v, o);
    return v;
}

// this warp's 4 probe buckets (2 warps/particle; half = z offset 0/1)
struct Probe4 { int n[4]; int s4[4]; };
__device__ __forceinline__ Probe4 probe_setup(const int* s_cnt,
                                              float px, float py, float pz,
                                              int half) {
    Probe4 pr;
    int iz = pcoord(pz, half);                           // clamped 0..7
#pragma unroll
    for (int k = 0; k < 4; ++k) {
        int h = bidx3(pcoord(px, k & 1), pcoord(py, (k >> 1) & 1), iz);
        pr.n[k]  = s_cnt[h];                             // h < 512 always
        pr.s4[k] = h * CAP;
    }
    return pr;
}

// ---------------------------------------------------------------------------
// fused persistent kernel: predict | 3x(lambda|delta) | xsph, gbar between
// ---------------------------------------------------------------------------
__global__ void __launch_bounds__(256, 2) k_fused(const float* __restrict__ locs,
                                                  const float* __restrict__ vel,
                                                  float* __restrict__ out, int N) {
    __shared__ int   s_cnt[NC];
    __shared__ float s_red[4][4];
    int tid   = threadIdx.x;
    int pslot = tid >> 6;
    int t64   = tid & 63;
    int half  = t64 >> 5;
    int lane  = tid & 31;

    // ---- phase 0: predict (cnt[0] zeroed by previous call's xsph phase) ----
    {
        int i = blockIdx.x * 256 + tid;
        if (i < N) {
            float vx = vel[3 * i + 0];
            float vy = vel[3 * i + 1] - 9.8f * DT_;
            float vz = vel[3 * i + 2];
            float nrm = sqrtf(vx * vx + vy * vy + vz * vz);
            float s = fminf(MAXV / (nrm + 1e-4f), 1.0f);
            float px = locs[3 * i + 0] + DT_ * vx * s;
            float py = locs[3 * i + 1] + DT_ * vy * s;
            float pz = locs[3 * i + 2] + DT_ * vz * s;
            g_px[i] = px; g_py[i] = py; g_pz[i] = pz;
            g_sidx[0][i] = grid_insert(0, px, py, pz);
        }
    }
    gbar();

    // ---- solver iterations ----
    for (int g = 0; g < 3; ++g) {
        // fill s_cnt for grid g (L2 loads); block 0 zeroes cnt[g+1]
        if (blockIdx.x == 0)
            for (int k = tid; k < NC; k += 256) g_cnt[g + 1][k] = 0;
        for (int k = tid; k < NC; k += 256)
            s_cnt[k] = min(__ldcg(&g_cnt[g][k]), CAP);
        __syncthreads();

        // ---- lambda (slot loads via __ldcg: slot.w mutated below) ----
        for (int grp = blockIdx.x; grp < NG; grp += gridDim.x) {
            if (tid < 16) ((float*)s_red)[tid] = 0.0f;   // full zero (16 floats)
            __syncthreads();
            int p = grp * 4 + pslot;
            float pxi = g_px[p], pyi = g_py[p], pzi = g_pz[p];
            Probe4 pr = probe_setup(s_cnt, pxi, pyi, pzi, half);
            const float4* sl = g_slot[g];

            float acc = 0.0f;
#define LBODY(S) { \
            float dx = pxi - (S).x, dy = pyi - (S).y, dz = pzi - (S).z;      \
            float d2 = dx * dx + dy * dy + dz * dz + EPS_;                   \
            float rinv = rsqrtf(d2);                                         \
            float d = d2 * rinv;                                             \
            float tt = fmaxf(R_ - d, 0.0f);                                  \
            acc += (SPIKY * tt) * (tt * tt); }
            float4 buf[4];
#pragma unroll
            for (int k = 0; k < 4; ++k)
                if (lane < pr.n[k]) buf[k] = __ldcg(sl + pr.s4[k] + lane);
#pragma unroll
            for (int k = 0; k < 4; ++k)
                if (lane < pr.n[k]) LBODY(buf[k]);
#pragma unroll
            for (int k = 0; k < 4; ++k)
                for (int t = 32 + lane; t < pr.n[k]; t += 32) {
                    float4 s = __ldcg(sl + pr.s4[k] + t);
                    LBODY(s);
                }
#undef LBODY
            acc = wred(acc);
            if (lane == 0) atomicAdd(&s_red[pslot][0], acc);
            __syncthreads();
            if (t64 == 0) {
                float lam = -((s_red[pslot][0] - W_SELF) - RHO0) * STIFF;
                g_lam[p] = lam;
                int si = g_sidx[g][p];
                if (si >= 0 && si < NC * CAP) g_slot[g][si].w = lam;
            }
            __syncthreads();
        }
        gbar();

        // ---- delta (reuse s_cnt) ----
        int doFinal = (g == 2);
        for (int grp = blockIdx.x; grp < NG; grp += gridDim.x) {
            if (tid < 16) ((float*)s_red)[tid] = 0.0f;   // FIX: full 16, stride-4 rows
            __syncthreads();
            int p = grp * 4 + pslot;
            float pxi = g_px[p], pyi = g_py[p], pzi = g_pz[p];
            float li = g_lam[p];
            Probe4 pr = probe_setup(s_cnt, pxi, pyi, pzi, half);
            const float4* sl = g_slot[g];

            float ax = 0.0f, ay = 0.0f, az = 0.0f;
#define DBODY(S) { \
            float dx = pxi - (S).x, dy = pyi - (S).y, dz = pzi - (S).z;      \
            float d2 = dx * dx + dy * dy + dz * dz + EPS_;                   \
            float rinv = rsqrtf(d2);                                         \
            float d = d2 * rinv;                                             \
            float tt = fmaxf(R_ - d, 0.0f);                                  \
            float coef = (li + (S).w) * (NSPIKY3 * (tt * tt)) * rinv;        \
            ax += coef * dx; ay += coef * dy; az += coef * dz; }
            float4 buf[4];
#pragma unroll
            for (int k = 0; k < 4; ++k)
                if (lane < pr.n[k]) buf[k] = __ldcg(sl + pr.s4[k] + lane);
#pragma unroll
            for (int k = 0; k < 4; ++k)
                if (lane < pr.n[k]) DBODY(buf[k]);
#pragma unroll
            for (int k = 0; k < 4; ++k)
                for (int t = 32 + lane; t < pr.n[k]; t += 32) {
                    float4 s = __ldcg(sl + pr.s4[k] + t);
                    DBODY(s);
                }
#undef DBODY
            ax = wred(ax); ay = wred(ay); az = wred(az);
            if (lane == 0) {
                atomicAdd(&s_red[pslot][0], ax);
                atomicAdd(&s_red[pslot][1], ay);
                atomicAdd(&s_red[pslot][2], az);
            }
            __syncthreads();
            if (t64 == 0) {
                float nx = pxi + s_red[pslot][0];
                float ny = pyi + s_red[pslot][1];
                float nz = pzi + s_red[pslot][2];
                g_px[p] = nx; g_py[p] = ny; g_pz[p] = nz;
                int si = grid_insert(g + 1, nx, ny, nz);
                g_sidx[g + 1][p] = si;
                if (doFinal) {
                    float vx = (nx - locs[3 * p + 0]) * (1.0f / DT_);
                    float vy = (ny - locs[3 * p + 1]) * (1.0f / DT_);
                    float vz = (nz - locs[3 * p + 2]) * (1.0f / DT_);
                    g_nvx[p] = vx; g_nvy[p] = vy; g_nvz[p] = vz;
                    if (si >= 0 && si < NC * CAP)
                        g_nvslot[si] = make_float4(vx, vy, vz, 0.0f);
                    out[3 * p + 0] = nx;
                    out[3 * p + 1] = ny;
                    out[3 * p + 2] = nz;
                }
            }
            __syncthreads();
        }
        gbar();
    }

    // ---- xsph on grid 3; block 0 zeroes cnt[0] for the next call ----
    if (blockIdx.x == 0)
        for (int k = tid; k < NC; k += 256) g_cnt[0][k] = 0;
    for (int k = tid; k < NC; k += 256)
        s_cnt[k] = min(__ldcg(&g_cnt[3][k]), CAP);
    __syncthreads();

    for (int grp = blockIdx.x; grp < NG; grp += gridDim.x) {
        if (tid < 16) ((float*)s_red)[tid] = 0.0f;
        __syncthreads();
        int p = grp * 4 + pslot;
        float pxi = g_px[p], pyi = g_py[p], pzi = g_pz[p];
        Probe4 pr = probe_setup(s_cnt, pxi, pyi, pzi, half);
        const float4* sl = g_slot[3];

        float ws = 0.0f, wx = 0.0f, wy = 0.0f, wz = 0.0f;
#define XBODY(S, V) { \
        float dx = pxi - (S).x, dy = pyi - (S).y, dz = pzi - (S).z;          \
        float d2 = dx * dx + dy * dy + dz * dz + EPS_;                       \
        float rinv = rsqrtf(d2);                                             \
        float d = d2 * rinv;                                                 \
        float tt = fmaxf(R_ - d, 0.0f);                                      \
        float wk = (SPIKY * tt) * (tt * tt);                                 \
        ws += wk; wx += wk * (V).x; wy += wk * (V).y; wz += wk * (V).z; }
        float4 buf[4], vbuf[4];
#pragma unroll
        for (int k = 0; k < 4; ++k)
            if (lane < pr.n[k]) {
                buf[k]  = __ldcg(sl + pr.s4[k] + lane);
                vbuf[k] = __ldcg(g_nvslot + pr.s4[k] + lane);
            }
#pragma unroll
        for (int k = 0; k < 4; ++k)
            if (lane < pr.n[k]) XBODY(buf[k], vbuf[k]);
#pragma unroll
        for (int k = 0; k < 4; ++k)
            for (int t = 32 + lane; t < pr.n[k]; t += 32) {
                float4 s = __ldcg(sl + pr.s4[k] + t);
                float4 v = __ldcg(g_nvslot + pr.s4[k] + t);
                XBODY(s, v);
            }
#undef XBODY
        ws = wred(ws); wx = wred(wx); wy = wred(wy); wz = wred(wz);
        if (lane == 0) {
            atomicAdd(&s_red[pslot][0], ws);
            atomicAdd(&s_red[pslot][1], wx);
            atomicAdd(&s_red[pslot][2], wy);
            atomicAdd(&s_red[pslot][3], wz);
        }
        __syncthreads();
        if (t64 == 0) {
            float S = s_red[pslot][0];
            float vix = g_nvx[p], viy = g_nvy[p], viz = g_nvz[p];
            float nx = vix + VDTR * (s_red[pslot][1] - S * vix);
            float ny = viy + VDTR * (s_red[pslot][2] - S * viy);
            float nz = viz + VDTR * (s_red[pslot][3] - S * viz);
            float nrm = sqrtf(nx * nx + ny * ny + nz * nz);
            float sc = fminf(MAXV / (nrm + 1e-4f), 1.0f);
            out[3 * N + 3 * p + 0] = nx * sc;
            out[3 * N + 3 * p + 1] = ny * sc;
            out[3 * N + 3 * p + 2] = nz * sc;
        }
        __syncthreads();
    }
}

// ---------------------------------------------------------------------------
extern "C" void kernel_launch(void* const* d_in, const int* in_sizes, int n_in,
                              void* d_out, int out_size) {
    const float* locs = (const float*)d_in[0];
    const float* vel  = (const float*)d_in[1];
    float* out = (float*)d_out;
    int N = in_sizes[0] / 3;  // 4096

    k_fused<<<NBLK, 256>>>(locs, vel, out, N);
}

// round 15
// speedup vs baseline: 1.4162x; 1.4162x over previous
#include <cuda_runtime.h>

#define NP   4096   // particle capacity
#define NCX  8      // 8^3 cells of size 2R
#define NC   512
#define CAP  96     // slots per cell (mean ~33 for this data)
#define NBLK 512    // persistent blocks (4/SM guaranteed -> 592 slots >= 512)
#define NPB  8      // particles per block (1 warp each)

static constexpr float R_      = 0.1f;
static constexpr float DT_     = 1.0f / 60.0f;
static constexpr float MAXV    = 3.0f;                 // 0.5*0.1/DT
static constexpr float RHO0    = 17510.1f;
static constexpr float STIFF   = 2.99e-11f;
static constexpr float SPIKY   = 4.774648292756860e6f; // 15/(pi*R^6)
static constexpr float NSPIKY3 = -3.0f * 4.774648292756860e6f;
static constexpr float VDTR    = 60.0f * (1.0f / 60.0f) / 17510.1f; // VISC*DT/RHO0
static constexpr float EPS_    = 1e-8f;
// self-pair contribution to rho: d_self = sqrt(EPS) = 1e-4, t = R - 1e-4
static constexpr float W_SELF  =
    (float)(4.774648292756860e6 * 0.0999 * 0.0999 * 0.0999);

// ---------------- scratch (device globals: allocation-guard safe) -----------
__device__ float    g_px[NP], g_py[NP], g_pz[NP];   // current pred (orig order)
__device__ float    g_lam[NP];
__device__ float    g_nvx[NP], g_nvy[NP], g_nvz[NP];
__device__ int      g_cnt[4][NC];                   // per-grid counts (zero-init)
__device__ float4   g_slot[4][NC * CAP];            // pos.xyz + (lambda in .w)
__device__ int      g_sidx[4][NP];                  // particle -> slot index
__device__ float4   g_nvslot[NC * CAP];             // new_vel slots (grid 3)
__device__ int      g_bar_cnt;                      // global barrier state
__device__ unsigned g_bar_gen;

// ---------------- global barrier (sense-reversing, device-scope) ------------
__device__ __forceinline__ void gbar() {
    __syncthreads();
    if (threadIdx.x == 0) {
        __threadfence();
        unsigned gen = *(volatile unsigned*)&g_bar_gen;
        if (atomicAdd(&g_bar_cnt, 1) == (int)gridDim.x - 1) {
            atomicExch(&g_bar_cnt, 0);
            __threadfence();
            atomicAdd(&g_bar_gen, 1u);
        } else {
            while (*(volatile unsigned*)&g_bar_gen == gen) { __nanosleep(64); }
            __threadfence();    // acquire
        }
    }
    __syncthreads();
}

// ---------------- cell helpers (cell size = 2R = 0.2) -----------------------
// every coordinate clamped AT USE: h < 512 for ANY input bits
__device__ __forceinline__ int clampi(int v) { return min(max(v, 0), NCX - 1); }
__device__ __forceinline__ int ccell(float x) {          // insertion cell
    return clampi(__float2int_rd(x * 5.0f) + 1);
}
__device__ __forceinline__ int pcoord(float x, int d) {  // probe cell, clamped
    return clampi(__float2int_rd(x * 5.0f - 0.5f) + 1 + d);
}
__device__ __forceinline__ int bidx3(int ix, int iy, int iz) {
    return ix | (iy << 3) | (iz << 6);
}
__device__ __forceinline__ int grid_insert(int g, float x, float y, float z) {
    int h = bidx3(ccell(x), ccell(y), ccell(z));
    int s = atomicAdd(&g_cnt[g][h], 1);
    if (s >= CAP) return -1;
    int si = h * CAP + s;
    g_slot[g][si] = make_float4(x, y, z, 0.0f);
    return si;
}

__device__ __forceinline__ float wred(float v) {
#pragma unroll
    for (int o = 16; o; o >>= 1) v += __shfl_xor_sync(0xffffffffu, v, o);
    return v;
}

// one z-layer of the 2x2x2 probe: 4 buckets
struct Probe4 { int n[4]; int s4[4]; };
__device__ __forceinline__ Probe4 probe_setup(const int* s_cnt,
                                              float px, float py, float pz,
                                              int half) {
    Probe4 pr;
    int iz = pcoord(pz, half);
#pragma unroll
    for (int k = 0; k < 4; ++k) {
        int h = bidx3(pcoord(px, k & 1), pcoord(py, (k >> 1) & 1), iz);
        pr.n[k]  = s_cnt[h];
        pr.s4[k] = h * CAP;
    }
    return pr;
}

// ---------------------------------------------------------------------------
// fused persistent kernel: predict | 3x(lambda|delta) | xsph, gbar between.
// warp-per-particle everywhere; no intra-phase block syncs.
// ---------------------------------------------------------------------------
__global__ void __launch_bounds__(256, 4) k_fused(const float* __restrict__ locs,
                                                  const float* __restrict__ vel,
                                                  float* __restrict__ out, int N) {
    __shared__ int s_cnt[NC];
    int tid  = threadIdx.x;
    int wid  = tid >> 5;
    int lane = tid & 31;
    int p    = blockIdx.x * NPB + wid;     // this warp's particle (< 4096)

    // ---- phase 0: predict (cnt[0] zeroed by previous call's xsph) ----
    if (lane == 0 && p < N) {
        float vx = vel[3 * p + 0];
        float vy = vel[3 * p + 1] - 9.8f * DT_;
        float vz = vel[3 * p + 2];
        float nrm = sqrtf(vx * vx + vy * vy + vz * vz);
        float s = fminf(MAXV / (nrm + 1e-4f), 1.0f);
        float px = locs[3 * p + 0] + DT_ * vx * s;
        float py = locs[3 * p + 1] + DT_ * vy * s;
        float pz = locs[3 * p + 2] + DT_ * vz * s;
        g_px[p] = px; g_py[p] = py; g_pz[p] = pz;
        g_sidx[0][p] = grid_insert(0, px, py, pz);
    }
    gbar();

    // ---- solver iterations ----
    for (int g = 0; g < 3; ++g) {
        // fill s_cnt for grid g; block 0 zeroes cnt[g+1] (read after next gbar)
        if (blockIdx.x == 0)
            for (int k = tid; k < NC; k += 256) g_cnt[g + 1][k] = 0;
        for (int k = tid; k < NC; k += 256)
            s_cnt[k] = min(__ldcg(&g_cnt[g][k]), CAP);
        __syncthreads();

        const float4* sl = g_slot[g];
        float pxi = g_px[p], pyi = g_py[p], pzi = g_pz[p];

        // ---- lambda ----
        {
            float acc = 0.0f;
#define LBODY(S) { \
            float dx = pxi - (S).x, dy = pyi - (S).y, dz = pzi - (S).z;      \
            float d2 = dx * dx + dy * dy + dz * dz + EPS_;                   \
            float rinv = rsqrtf(d2);                                         \
            float d = d2 * rinv;                                             \
            float tt = fmaxf(R_ - d, 0.0f);                                  \
            acc += (SPIKY * tt) * (tt * tt); }
#pragma unroll
            for (int half = 0; half < 2; ++half) {
                Probe4 pr = probe_setup(s_cnt, pxi, pyi, pzi, half);
#pragma unroll
                for (int k = 0; k < 4; ++k)
                    for (int t = lane; t < pr.n[k]; t += 32) {
                        float4 s = __ldcg(sl + pr.s4[k] + t);
                        LBODY(s);
                    }
            }
#undef LBODY
            acc = wred(acc);
            if (lane == 0) {
                float lam = -((acc - W_SELF) - RHO0) * STIFF;
                g_lam[p] = lam;
                int si = g_sidx[g][p];
                if (si >= 0 && si < NC * CAP) g_slot[g][si].w = lam;
            }
        }
        gbar();

        // ---- delta (s_cnt persists across the gbar) ----
        {
            float li = g_lam[p];
            float ax = 0.0f, ay = 0.0f, az = 0.0f;
#define DBODY(S) { \
            float dx = pxi - (S).x, dy = pyi - (S).y, dz = pzi - (S).z;      \
            float d2 = dx * dx + dy * dy + dz * dz + EPS_;                   \
            float rinv = rsqrtf(d2);                                         \
            float d = d2 * rinv;                                             \
            float tt = fmaxf(R_ - d, 0.0f);                                  \
            float coef = (li + (S).w) * (NSPIKY3 * (tt * tt)) * rinv;        \
            ax += coef * dx; ay += coef * dy; az += coef * dz; }
#pragma unroll
            for (int half = 0; half < 2; ++half) {
                Probe4 pr = probe_setup(s_cnt, pxi, pyi, pzi, half);
#pragma unroll
                for (int k = 0; k < 4; ++k)
                    for (int t = lane; t < pr.n[k]; t += 32) {
                        float4 s = __ldcg(sl + pr.s4[k] + t);
                        DBODY(s);
                    }
            }
#undef DBODY
            ax = wred(ax); ay = wred(ay); az = wred(az);
            if (lane == 0) {
                float nx = pxi + ax, ny = pyi + ay, nz = pzi + az;
                g_px[p] = nx; g_py[p] = ny; g_pz[p] = nz;
                int si = grid_insert(g + 1, nx, ny, nz);
                g_sidx[g + 1][p] = si;
                if (g == 2) {
                    float vx = (nx - locs[3 * p + 0]) * (1.0f / DT_);
                    float vy = (ny - locs[3 * p + 1]) * (1.0f / DT_);
                    float vz = (nz - locs[3 * p + 2]) * (1.0f / DT_);
                    g_nvx[p] = vx; g_nvy[p] = vy; g_nvz[p] = vz;
                    if (si >= 0 && si < NC * CAP)
                        g_nvslot[si] = make_float4(vx, vy, vz, 0.0f);
                    out[3 * p + 0] = nx;
                    out[3 * p + 1] = ny;
                    out[3 * p + 2] = nz;
                }
            }
        }
        gbar();
    }

    // ---- xsph on grid 3; block 0 zeroes cnt[0] for the next call ----
    if (blockIdx.x == 0)
        for (int k = tid; k < NC; k += 256) g_cnt[0][k] = 0;
    for (int k = tid; k < NC; k += 256)
        s_cnt[k] = min(__ldcg(&g_cnt[3][k]), CAP);
    __syncthreads();

    {
        const float4* sl = g_slot[3];
        float pxi = g_px[p], pyi = g_py[p], pzi = g_pz[p];
        float ws = 0.0f, wx = 0.0f, wy = 0.0f, wz = 0.0f;
#define XBODY(S, V) { \
        float dx = pxi - (S).x, dy = pyi - (S).y, dz = pzi - (S).z;          \
        float d2 = dx * dx + dy * dy + dz * dz + EPS_;                       \
        float rinv = rsqrtf(d2);                                             \
        float d = d2 * rinv;                                                 \
        float tt = fmaxf(R_ - d, 0.0f);                                      \
        float wk = (SPIKY * tt) * (tt * tt);                                 \
        ws += wk; wx += wk * (V).x; wy += wk * (V).y; wz += wk * (V).z; }
#pragma unroll
        for (int half = 0; half < 2; ++half) {
            Probe4 pr = probe_setup(s_cnt, pxi, pyi, pzi, half);
#pragma unroll
            for (int k = 0; k < 4; ++k)
                for (int t = lane; t < pr.n[k]; t += 32) {
                    float4 s = __ldcg(sl + pr.s4[k] + t);
                    float4 v = __ldcg(g_nvslot + pr.s4[k] + t);
                    XBODY(s, v);
                }
        }
#undef XBODY
        ws = wred(ws); wx = wred(wx); wy = wred(wy); wz = wred(wz);
        if (lane == 0) {
            float vix = g_nvx[p], viy = g_nvy[p], viz = g_nvz[p];
            float nx = vix + VDTR * (wx - ws * vix);
            float ny = viy + VDTR * (wy - ws * viy);
            float nz = viz + VDTR * (wz - ws * viz);
            float nrm = sqrtf(nx * nx + ny * ny + nz * nz);
            float sc = fminf(MAXV / (nrm + 1e-4f), 1.0f);
            out[3 * N + 3 * p + 0] = nx * sc;
            out[3 * N + 3 * p + 1] = ny * sc;
            out[3 * N + 3 * p + 2] = nz * sc;
        }
    }
}

// ---------------------------------------------------------------------------
extern "C" void kernel_launch(void* const* d_in, const int* in_sizes, int n_in,
                              void* d_out, int out_size) {
    const float* locs = (const float*)d_in[0];
    const float* vel  = (const float*)d_in[1];
    float* out = (float*)d_out;
    int N = in_sizes[0] / 3;  // 4096

    k_fused<<<NBLK, 256>>>(locs, vel, out, N);
}

// round 17
// speedup vs baseline: 1.4623x; 1.0325x over previous
#include <cuda_runtime.h>

#define NP   4096   // particle capacity
#define NCX  8      // 8^3 cells of size 2R
#define NC   512
#define CAP  96     // slots per cell (mean ~33 for this data)
#define NBLK 512    // persistent blocks (4/SM -> 592 slots >= 512, co-resident)
#define NPB  8      // particles per block (2 subs x 4, 2 warps each)

static constexpr float R_      = 0.1f;
static constexpr float DT_     = 1.0f / 60.0f;
static constexpr float MAXV    = 3.0f;                 // 0.5*0.1/DT
static constexpr float RHO0    = 17510.1f;
static constexpr float STIFF   = 2.99e-11f;
static constexpr float SPIKY   = 4.774648292756860e6f; // 15/(pi*R^6)
static constexpr float NSPIKY3 = -3.0f * 4.774648292756860e6f;
static constexpr float VDTR    = 60.0f * (1.0f / 60.0f) / 17510.1f; // VISC*DT/RHO0
static constexpr float EPS_    = 1e-8f;
// self-pair contribution to rho: d_self = sqrt(EPS) = 1e-4, t = R - 1e-4
static constexpr float W_SELF  =
    (float)(4.774648292756860e6 * 0.0999 * 0.0999 * 0.0999);

// ---------------- scratch (device globals: allocation-guard safe) -----------
__device__ float    g_px[NP], g_py[NP], g_pz[NP];
__device__ float    g_lam[NP];
__device__ float    g_nvx[NP], g_nvy[NP], g_nvz[NP];
__device__ int      g_cnt[4][NC];                   // zero-init
__device__ float4   g_slot[4][NC * CAP];            // pos.xyz + lambda in .w
__device__ int      g_sidx[4][NP];
__device__ float4   g_nvslot[NC * CAP];
__device__ int      g_bar_cnt;
__device__ unsigned g_bar_gen;

// ---------------- global barrier (sense-reversing) ---------------------------
__device__ __forceinline__ void gbar() {
    __syncthreads();
    if (threadIdx.x == 0) {
        __threadfence();
        unsigned gen = *(volatile unsigned*)&g_bar_gen;
        if (atomicAdd(&g_bar_cnt, 1) == (int)gridDim.x - 1) {
            atomicExch(&g_bar_cnt, 0);
            __threadfence();
            atomicAdd(&g_bar_gen, 1u);
        } else {
            while (*(volatile unsigned*)&g_bar_gen == gen) { __nanosleep(32); }
            __threadfence();
        }
    }
    __syncthreads();
}

// ---------------- cell helpers (cell = 2R = 0.2); clamped at use -------------
__device__ __forceinline__ int clampi(int v) { return min(max(v, 0), NCX - 1); }
__device__ __forceinline__ int ccell(float x) {
    return clampi(__float2int_rd(x * 5.0f) + 1);
}
__device__ __forceinline__ int pcoord(float x, int d) {
    return clampi(__float2int_rd(x * 5.0f - 0.5f) + 1 + d);
}
__device__ __forceinline__ int bidx3(int ix, int iy, int iz) {
    return ix | (iy << 3) | (iz << 6);
}
__device__ __forceinline__ int grid_insert(int g, float x, float y, float z) {
    int h = bidx3(ccell(x), ccell(y), ccell(z));
    int s = atomicAdd(&g_cnt[g][h], 1);
    if (s >= CAP) return -1;
    int si = h * CAP + s;
    g_slot[g][si] = make_float4(x, y, z, 0.0f);
    return si;
}

__device__ __forceinline__ float wred(float v) {
#pragma unroll
    for (int o = 16; o; o >>= 1) v += __shfl_xor_sync(0xffffffffu, v, o);
    return v;
}

struct Probe4 { int n[4]; int s4[4]; };
__device__ __forceinline__ Probe4 probe_setup(const int* s_cnt,
                                              float px, float py, float pz,
                                              int half) {
    Probe4 pr;
    int iz = pcoord(pz, half);
#pragma unroll
    for (int k = 0; k < 4; ++k) {
        int h = bidx3(pcoord(px, k & 1), pcoord(py, (k >> 1) & 1), iz);
        pr.n[k]  = s_cnt[h];
        pr.s4[k] = h * CAP;
    }
    return pr;
}

// ---------------------------------------------------------------------------
// fused persistent kernel: predict | 3x(lambda|delta) | xsph.
// 2 warps/particle, 4 particles per sub, 2 subs per block (8 particles).
// ---------------------------------------------------------------------------
__global__ void __launch_bounds__(256, 4) k_fused(const float* __restrict__ locs,
                                                  const float* __restrict__ vel,
                                                  float* __restrict__ out, int N) {
    __shared__ int   s_cnt[NC];
    __shared__ float s_red[NPB][4];      // row = sub*4 + ps
    int tid  = threadIdx.x;
    int wid  = tid >> 5;
    int lane = tid & 31;
    int ps   = wid >> 1;                 // 0..3
    int half = wid & 1;                  // z-layer of 2x2x2 probe
    int base = blockIdx.x * NPB;
    bool leader = (half == 0 && lane == 0);

    // ---- phase 0: predict (cnt[0] zeroed by previous call's xsph) ----
    if (tid < NPB) {
        int i = base + tid;
        if (i < N) {
            float vx = vel[3 * i + 0];
            float vy = vel[3 * i + 1] - 9.8f * DT_;
            float vz = vel[3 * i + 2];
            float nrm = sqrtf(vx * vx + vy * vy + vz * vz);
            float s = fminf(MAXV / (nrm + 1e-4f), 1.0f);
            float px = locs[3 * i + 0] + DT_ * vx * s;
            float py = locs[3 * i + 1] + DT_ * vy * s;
            float pz = locs[3 * i + 2] + DT_ * vz * s;
            g_px[i] = px; g_py[i] = py; g_pz[i] = pz;
            g_sidx[0][i] = grid_insert(0, px, py, pz);
        }
    }
    gbar();

    // ---- solver iterations ----
    for (int g = 0; g < 3; ++g) {
        if (blockIdx.x == 0)
            for (int k = tid; k < NC; k += 256) g_cnt[g + 1][k] = 0;
        for (int k = tid; k < NC; k += 256)
            s_cnt[k] = min(__ldcg(&g_cnt[g][k]), CAP);
        if (tid < 4 * NPB) ((float*)s_red)[tid] = 0.0f;
        __syncthreads();

        const float4* sl = g_slot[g];

        // ---- lambda: 2 subs, then one sync, then finalize both ----
#pragma unroll
        for (int sub = 0; sub < 2; ++sub) {
            int p = base + sub * 4 + ps;
            float pxi = g_px[p], pyi = g_py[p], pzi = g_pz[p];
            Probe4 pr = probe_setup(s_cnt, pxi, pyi, pzi, half);
            float acc = 0.0f;
#define LBODY(S) { \
            float dx = pxi - (S).x, dy = pyi - (S).y, dz = pzi - (S).z;      \
            float d2 = dx * dx + dy * dy + dz * dz + EPS_;                   \
            float rinv = rsqrtf(d2);                                         \
            float d = d2 * rinv;                                             \
            float tt = fmaxf(R_ - d, 0.0f);                                  \
            acc += (SPIKY * tt) * (tt * tt); }
            float4 b0[4];
#pragma unroll
            for (int k = 0; k < 4; ++k)
                if (lane < pr.n[k]) b0[k] = __ldcg(sl + pr.s4[k] + lane);
#pragma unroll
            for (int k = 0; k < 4; ++k) {
                if (lane < pr.n[k]) LBODY(b0[k]);
                for (int t = 32 + lane; t < pr.n[k]; t += 32) {
                    float4 s = __ldcg(sl + pr.s4[k] + t);
                    LBODY(s);
                }
            }
#undef LBODY
            acc = wred(acc);
            if (lane == 0) atomicAdd(&s_red[sub * 4 + ps][0], acc);
        }
        __syncthreads();
        if (leader) {
#pragma unroll
            for (int sub = 0; sub < 2; ++sub) {
                int p = base + sub * 4 + ps;
                float lam = -((s_red[sub * 4 + ps][0] - W_SELF) - RHO0) * STIFF;
                g_lam[p] = lam;
                int si = g_sidx[g][p];
                if (si >= 0 && si < NC * CAP) g_slot[g][si].w = lam;
            }
        }
        gbar();

        // ---- delta ----
        if (tid < 4 * NPB) ((float*)s_red)[tid] = 0.0f;
        __syncthreads();
#pragma unroll
        for (int sub = 0; sub < 2; ++sub) {
            int p = base + sub * 4 + ps;
            float pxi = g_px[p], pyi = g_py[p], pzi = g_pz[p];
            float li = g_lam[p];
            Probe4 pr = probe_setup(s_cnt, pxi, pyi, pzi, half);
            float ax = 0.0f, ay = 0.0f, az = 0.0f;
#define DBODY(S) { \
            float dx = pxi - (S).x, dy = pyi - (S).y, dz = pzi - (S).z;      \
            float d2 = dx * dx + dy * dy + dz * dz + EPS_;                   \
            float rinv = rsqrtf(d2);                                         \
            float d = d2 * rinv;                                             \
            float tt = fmaxf(R_ - d, 0.0f);                                  \
            float coef = (li + (S).w) * (NSPIKY3 * (tt * tt)) * rinv;        \
            ax += coef * dx; ay += coef * dy; az += coef * dz; }
            float4 b0[4];
#pragma unroll
            for (int k = 0; k < 4; ++k)
                if (lane < pr.n[k]) b0[k] = __ldcg(sl + pr.s4[k] + lane);
#pragma unroll
            for (int k = 0; k < 4; ++k) {
                if (lane < pr.n[k]) DBODY(b0[k]);
                for (int t = 32 + lane; t < pr.n[k]; t += 32) {
                    float4 s = __ldcg(sl + pr.s4[k] + t);
                    DBODY(s);
                }
            }
#undef DBODY
            ax = wred(ax); ay = wred(ay); az = wred(az);
            if (lane == 0) {
                atomicAdd(&s_red[sub * 4 + ps][0], ax);
                atomicAdd(&s_red[sub * 4 + ps][1], ay);
                atomicAdd(&s_red[sub * 4 + ps][2], az);
            }
        }
        __syncthreads();
        if (leader) {
#pragma unroll
            for (int sub = 0; sub < 2; ++sub) {
                int p = base + sub * 4 + ps;
                int row = sub * 4 + ps;
                float nx = g_px[p] + s_red[row][0];
                float ny = g_py[p] + s_red[row][1];
                float nz = g_pz[p] + s_red[row][2];
                g_px[p] = nx; g_py[p] = ny; g_pz[p] = nz;
                int si = grid_insert(g + 1, nx, ny, nz);
                g_sidx[g + 1][p] = si;
                if (g == 2) {
                    float vx = (nx - locs[3 * p + 0]) * (1.0f / DT_);
                    float vy = (ny - locs[3 * p + 1]) * (1.0f / DT_);
                    float vz = (nz - locs[3 * p + 2]) * (1.0f / DT_);
                    g_nvx[p] = vx; g_nvy[p] = vy; g_nvz[p] = vz;
                    if (si >= 0 && si < NC * CAP)
                        g_nvslot[si] = make_float4(vx, vy, vz, 0.0f);
                    out[3 * p + 0] = nx;
                    out[3 * p + 1] = ny;
                    out[3 * p + 2] = nz;
                }
            }
        }
        gbar();
    }

    // ---- xsph on grid 3; block 0 zeroes cnt[0] for next call ----
    if (blockIdx.x == 0)
        for (int k = tid; k < NC; k += 256) g_cnt[0][k] = 0;
    for (int k = tid; k < NC; k += 256)
        s_cnt[k] = min(__ldcg(&g_cnt[3][k]), CAP);
    if (tid < 4 * NPB) ((float*)s_red)[tid] = 0.0f;
    __syncthreads();

    {
        const float4* sl = g_slot[3];
#pragma unroll
        for (int sub = 0; sub < 2; ++sub) {
            int p = base + sub * 4 + ps;
            float pxi = g_px[p], pyi = g_py[p], pzi = g_pz[p];
            Probe4 pr = probe_setup(s_cnt, pxi, pyi, pzi, half);
            float ws = 0.0f, wx = 0.0f, wy = 0.0f, wz = 0.0f;
#define XBODY(S, V) { \
            float dx = pxi - (S).x, dy = pyi - (S).y, dz = pzi - (S).z;      \
            float d2 = dx * dx + dy * dy + dz * dz + EPS_;                   \
            float rinv = rsqrtf(d2);                                         \
            float d = d2 * rinv;                                             \
            float tt = fmaxf(R_ - d, 0.0f);                                  \
            float wk = (SPIKY * tt) * (tt * tt);                             \
            ws += wk; wx += wk * (V).x; wy += wk * (V).y; wz += wk * (V).z; }
            float4 b0[4], v0[4];
#pragma unroll
            for (int k = 0; k < 4; ++k)
                if (lane < pr.n[k]) {
                    b0[k] = __ldcg(sl + pr.s4[k] + lane);
                    v0[k] = __ldcg(g_nvslot + pr.s4[k] + lane);
                }
#pragma unroll
            for (int k = 0; k < 4; ++k) {
                if (lane < pr.n[k]) XBODY(b0[k], v0[k]);
                for (int t = 32 + lane; t < pr.n[k]; t += 32) {
                    float4 s = __ldcg(sl + pr.s4[k] + t);
                    float4 v = __ldcg(g_nvslot + pr.s4[k] + t);
                    XBODY(s, v);
                }
            }
#undef XBODY
            ws = wred(ws); wx = wred(wx); wy = wred(wy); wz = wred(wz);
            if (lane == 0) {
                atomicAdd(&s_red[sub * 4 + ps][0], ws);
                atomicAdd(&s_red[sub * 4 + ps][1], wx);
                atomicAdd(&s_red[sub * 4 + ps][2], wy);
                atomicAdd(&s_red[sub * 4 + ps][3], wz);
            }
        }
        __syncthreads();
        if (leader) {
#pragma unroll
            for (int sub = 0; sub < 2; ++sub) {
                int p = base + sub * 4 + ps;
                int row = sub * 4 + ps;
                float S = s_red[row][0];
                float vix = g_nvx[p], viy = g_nvy[p], viz = g_nvz[p];
                float nx = vix + VDTR * (s_red[row][1] - S * vix);
                float ny = viy + VDTR * (s_red[row][2] - S * viy);
                float nz = viz + VDTR * (s_red[row][3] - S * viz);
                float nrm = sqrtf(nx * nx + ny * ny + nz * nz);
                float sc = fminf(MAXV / (nrm + 1e-4f), 1.0f);
                out[3 * N + 3 * p + 0] = nx * sc;
                out[3 * N + 3 * p + 1] = ny * sc;
                out[3 * N + 3 * p + 2] = nz * sc;
            }
        }
    }
}

// ---------------------------------------------------------------------------
extern "C" void kernel_launch(void* const* d_in, const int* in_sizes, int n_in,
                              void* d_out, int out_size) {
    const float* locs = (const float*)d_in[0];
    const float* vel  = (const float*)d_in[1];
    float* out = (float*)d_out;
    int N = in_sizes[0] / 3;  // 4096

    k_fused<<<NBLK, 256>>>(locs, vel, out, N);
}